// round 6
// baseline (speedup 1.0000x reference)
#include <cuda_runtime.h>
#include <cstdint>

typedef unsigned long long u64;

#define GROUPS 8
#define CDIM 32
#define ROWS_PER_GROUP 262144
#define TOTAL_ROWS (GROUPS * ROWS_PER_GROUP)
#define EPSV 1e-5f
#define TITER 5

// ---- pass 1 config ----
#define P1_BLOCKS_PER_GROUP 256
#define P1_GRID (GROUPS * P1_BLOCKS_PER_GROUP)   // 2048
#define P1_ROWS 1024                             // rows per block
#define P1_WROWS 128                             // rows (samples) per warp
#define P1_CHUNK 16                              // samples per staged chunk
#define P1_CHUNKS (P1_WROWS / P1_CHUNK)          // 8
#define SSTRIDE 36                               // floats per staged sample (16B-aligned, LDS.32 conflict-free)
#define WBUF_F (P1_CHUNK * SSTRIDE)              // 576 floats = 2304 B per warp

// ---- reduction stage ----
#define RED_SLICES 32
#define RED_FOLD (P1_BLOCKS_PER_GROUP / RED_SLICES) // 8

// ---- pass 2 config ----
#define P2_ROWS 256
#define P2_TPB 128
#define P2_GRID (TOTAL_ROWS / P2_ROWS)           // 8192
#define ZST 34                                   // floats per staged row (8B-aligned LDS.64, 2-way max)

// ---- scratch ----
__device__ __align__(16) float gCovPart[P1_GRID * 1024];
__device__ __align__(16) float gSumPart[P1_GRID * 32];
__device__ __align__(16) float gCov2[GROUPS * RED_SLICES * 1024];
__device__ __align__(16) float gSum2[GROUPS * RED_SLICES * 32];
__device__ __align__(16) float gMt[GROUPS * 1024];   // Mt[g][d][c]
__device__ __align__(16) float gBias[GROUPS * 32];

// ---- f32x2 helpers ----
__device__ __forceinline__ u64 pack2(float a, float b) {
    u64 r; asm("mov.b64 %0, {%1, %2};" : "=l"(r) : "f"(a), "f"(b)); return r;
}
__device__ __forceinline__ float2 unpack2(u64 v) {
    float2 r; asm("mov.b64 {%0, %1}, %2;" : "=f"(r.x), "=f"(r.y) : "l"(v)); return r;
}
__device__ __forceinline__ u64 ffma2(u64 a, u64 b, u64 c) {
    u64 d; asm("fma.rn.f32x2 %0, %1, %2, %3;" : "=l"(d) : "l"(a), "l"(b), "l"(c)); return d;
}

// ============================================================================
// Kernel 1: partial C = sum z z^T + channel sums. UNIFORM-BROADCAST design.
// Lane l owns C row l (16 channel-paired f32x2 accumulators = 32 channels).
// Per sample: zi = z[s][l] (lane-distinct LDS.32, conflict-free) and the full
// 32-channel vector zj via 8 WARP-UNIFORM LDS.128 (true broadcast -> 1 wf each).
// 16 FFMA2 per sample per lane. Per-warp staging, register double-buffered.
// ============================================================================
__global__ __launch_bounds__(256, 3) void k1_stats(const float4* __restrict__ in4) {
    __shared__ __align__(16) unsigned char smem_raw[32768];
    float* red = (float*)smem_raw;

    const int t   = threadIdx.x;
    const int bid = blockIdx.x;
    const int w   = t >> 5;
    const int l   = t & 31;

    float* wst = (float*)(smem_raw + w * (WBUF_F * 4));   // 2304 B per warp

    u64 acc[16];
#pragma unroll
    for (int jp = 0; jp < 16; jp++) acc[jp] = 0ull;
    float msum = 0.f;                                     // channel = l

    const long wbase4 = (long)bid * (P1_ROWS * 8) + (long)w * (P1_WROWS * 8);

    // prefetch chunk 0: 16 samples = 128 float4; lane loads f = l + 32*kk
    float4 v[4];
#pragma unroll
    for (int kk = 0; kk < 4; kk++) v[kk] = in4[wbase4 + l + 32 * kk];

    for (int c = 0; c < P1_CHUNKS; c++) {
        __syncwarp();   // prior chunk's reads done before overwrite
        // ---- stage (row s, slot sl): 16B-aligned float4 stores ----
#pragma unroll
        for (int kk = 0; kk < 4; kk++) {
            int f = l + 32 * kk;
            int s = f >> 3, sl = f & 7;
            *(float4*)(wst + s * SSTRIDE + 4 * sl) = v[kk];
        }
        // ---- prefetch next chunk ----
        if (c + 1 < P1_CHUNKS) {
            long nb = wbase4 + (long)(c + 1) * (P1_CHUNK * 8);
#pragma unroll
            for (int kk = 0; kk < 4; kk++) v[kk] = in4[nb + l + 32 * kk];
        }
        __syncwarp();   // stores visible
        // ---- compute: per sample, uniform zj + lane zi ----
#pragma unroll
        for (int s = 0; s < P1_CHUNK; s++) {
            float zi = wst[s * SSTRIDE + l];
            msum += zi;
            u64 zz = pack2(zi, zi);
            const ulonglong2* zj = (const ulonglong2*)(wst + s * SSTRIDE);
#pragma unroll
            for (int q = 0; q < 8; q++) {
                ulonglong2 zq = zj[q];                    // warp-uniform -> broadcast
                acc[2 * q]     = ffma2(zz, zq.x, acc[2 * q]);
                acc[2 * q + 1] = ffma2(zz, zq.y, acc[2 * q + 1]);
            }
        }
    }
    __syncthreads();
    // ---- per-warp partials: lane l = row l of C ----
#pragma unroll
    for (int jp = 0; jp < 16; jp++) {
        float2 x = unpack2(acc[jp]);
        red[w * 1024 + l * 32 + 2 * jp]     = x.x;
        red[w * 1024 + l * 32 + 2 * jp + 1] = x.y;
    }
    __syncthreads();
    // ---- block reduce C (deterministic order) ----
#pragma unroll
    for (int r = 0; r < 4; r++) {
        int e = t + 256 * r;
        float s = 0.f;
#pragma unroll
        for (int ww = 0; ww < 8; ww++) s += red[ww * 1024 + e];
        gCovPart[(long)bid * 1024 + e] = s;
    }
    __syncthreads();
    // ---- block reduce channel sums (channel = lane) ----
    red[t] = msum;
    __syncthreads();
    if (t < 32) {
        float s = 0.f;
#pragma unroll
        for (int ww = 0; ww < 8; ww++) s += red[ww * 32 + t];
        gSumPart[bid * 32 + t] = s;
    }
}

// ============================================================================
// Kernel 1b: fold 2048 partials -> 256
// ============================================================================
__global__ __launch_bounds__(256) void k_red() {
    const int t = threadIdx.x;
    const int bid = blockIdx.x;
    const long base = (long)bid * RED_FOLD;

#pragma unroll
    for (int r = 0; r < 4; r++) {
        int e = t + 256 * r;
        float s = 0.f;
#pragma unroll
        for (int f = 0; f < RED_FOLD; f++) s += gCovPart[(base + f) * 1024 + e];
        gCov2[(long)bid * 1024 + e] = s;
    }
    if (t < 32) {
        float s = 0.f;
#pragma unroll
        for (int f = 0; f < RED_FOLD; f++) s += gSumPart[(base + f) * 32 + t];
        gSum2[bid * 32 + t] = s;
    }
}

// ============================================================================
// Kernel 2: final reduce, build S, normalize, Newton-Schulz, emit Mt+bias.
// ============================================================================
__global__ __launch_bounds__(1024) void k_solve() {
    __shared__ float S[1024], B[1024], T1[1024], T2[1024];
    __shared__ float mu[32];
    __shared__ float redw[32];
    __shared__ float normsh;

    const int t = threadIdx.x;
    const int g = blockIdx.x;
    const int i = t >> 5, j = t & 31;

    float cv = 0.f;
    const float* cp = gCov2 + (long)g * RED_SLICES * 1024;
#pragma unroll 8
    for (int bb = 0; bb < RED_SLICES; bb++) cv += cp[bb * 1024 + t];
    if (t < 32) {
        float s = 0.f;
        const float* sp = gSum2 + g * RED_SLICES * 32;
#pragma unroll 8
        for (int bb = 0; bb < RED_SLICES; bb++) s += sp[bb * 32 + t];
        mu[t] = s * (1.0f / (float)ROWS_PER_GROUP);
    }
    __syncthreads();

    float sij = cv - (float)ROWS_PER_GROUP * mu[i] * mu[j] + ((i == j) ? EPSV : 0.f);

    float v = sij * sij;
#pragma unroll
    for (int o = 16; o; o >>= 1) v += __shfl_xor_sync(0xffffffffu, v, o);
    if (j == 0) redw[i] = v;
    __syncthreads();
    if (t < 32) {
        float x = redw[t];
#pragma unroll
        for (int o = 16; o; o >>= 1) x += __shfl_xor_sync(0xffffffffu, x, o);
        if (t == 0) normsh = sqrtf(x);
    }
    __syncthreads();
    const float nrm = normsh;

    S[t] = sij / nrm;
    B[t] = (i == j) ? 1.f : 0.f;
    __syncthreads();

    for (int it = 0; it < TITER; it++) {
        float s1 = 0.f;
#pragma unroll
        for (int kk = 0; kk < 32; kk++) s1 += B[i * 32 + kk] * B[kk * 32 + j];
        T1[t] = s1; __syncthreads();
        float s2 = 0.f;
#pragma unroll
        for (int kk = 0; kk < 32; kk++) s2 += T1[i * 32 + kk] * B[kk * 32 + j];
        T2[t] = s2; __syncthreads();
        float s3 = 0.f;
#pragma unroll
        for (int kk = 0; kk < 32; kk++) s3 += T2[i * 32 + kk] * S[kk * 32 + j];
        float nb = 1.5f * B[t] - 0.5f * s3;
        __syncthreads();
        B[t] = nb;
        __syncthreads();
    }

    const float inv = rsqrtf(nrm);
    float mt = B[j * 32 + i] * inv;
    gMt[g * 1024 + t] = mt;
    T1[t] = mt;
    __syncthreads();
    if (t < 32) {
        float bsum = 0.f;
#pragma unroll
        for (int d = 0; d < 32; d++) bsum += mu[d] * T1[d * 32 + t];
        gBias[g * 32 + t] = -bsum;
    }
}

// ============================================================================
// Kernel 3: out[n] = z[n] @ Mt + bias. UNIFORM-BROADCAST design.
// 128 threads; thread owns 2 FULL output rows (r0 = 64w + l, r0 + 32) with
// 16 channel-paired f32x2 accumulators per row. Per d-pair: Mt rows read via
// 16 WARP-UNIFORM LDS.128 (broadcast, free-ish), z via 2 lane-distinct LDS.64.
// 64 FFMA2 per dp per thread -> heavily FMA/DRAM bound, L1 relieved.
// ============================================================================
__global__ __launch_bounds__(P2_TPB, 4) void k2_apply(const float4* __restrict__ in4,
                                                      float4* __restrict__ out4) {
    __shared__ __align__(16) float zbuf[P2_ROWS * ZST];  // 34816 B
    __shared__ __align__(16) u64 mt2u[512];              // [d][jp]
    __shared__ u64 bias2[16];

    const int t = threadIdx.x;
    const int w = t >> 5;
    const int l = t & 31;
    const int g = blockIdx.x >> 10;          // 1024 blocks per group

    const u64* mtg = (const u64*)gMt + g * 512;
#pragma unroll
    for (int i = 0; i < 4; i++) mt2u[t + 128 * i] = mtg[t + 128 * i];
    if (t < 16) bias2[t] = ((const u64*)gBias)[g * 16 + t];

    const long R0 = (long)blockIdx.x * P2_ROWS;

    // ---- stage 256 rows: coalesced LDG.128, 8B-aligned float2 smem stores ----
#pragma unroll
    for (int i = 0; i < 16; i++) {
        int f = t + 128 * i;                 // float4 id in tile
        int row = f >> 3, sl = f & 7;
        float4 v = in4[R0 * 8 + f];
        float2* d = (float2*)(zbuf + row * ZST + 4 * sl);
        d[0] = make_float2(v.x, v.y);
        d[1] = make_float2(v.z, v.w);
    }
    __syncthreads();

    const int r0 = 64 * w + l;               // rows r0, r0+32

    u64 acc[2][16];
#pragma unroll
    for (int jp = 0; jp < 16; jp++) { acc[0][jp] = bias2[jp]; acc[1][jp] = bias2[jp]; }

#pragma unroll 4
    for (int dp = 0; dp < 16; dp++) {
        const int d0 = 2 * dp;
        float2 za = *(const float2*)(zbuf + r0 * ZST + d0);
        float2 zb = *(const float2*)(zbuf + (r0 + 32) * ZST + d0);
        u64 za0 = pack2(za.x, za.x), za1 = pack2(za.y, za.y);
        u64 zb0 = pack2(zb.x, zb.x), zb1 = pack2(zb.y, zb.y);
        const ulonglong2* m0 = (const ulonglong2*)(mt2u + d0 * 16);        // uniform
        const ulonglong2* m1 = (const ulonglong2*)(mt2u + (d0 + 1) * 16);  // uniform
#pragma unroll
        for (int q = 0; q < 8; q++) {
            ulonglong2 a = m0[q];
            ulonglong2 b = m1[q];
            acc[0][2 * q]     = ffma2(za0, a.x, acc[0][2 * q]);
            acc[0][2 * q + 1] = ffma2(za0, a.y, acc[0][2 * q + 1]);
            acc[1][2 * q]     = ffma2(zb0, a.x, acc[1][2 * q]);
            acc[1][2 * q + 1] = ffma2(zb0, a.y, acc[1][2 * q + 1]);
            acc[0][2 * q]     = ffma2(za1, b.x, acc[0][2 * q]);
            acc[0][2 * q + 1] = ffma2(za1, b.y, acc[0][2 * q + 1]);
            acc[1][2 * q]     = ffma2(zb1, b.x, acc[1][2 * q]);
            acc[1][2 * q + 1] = ffma2(zb1, b.y, acc[1][2 * q + 1]);
        }
    }

#pragma unroll
    for (int r = 0; r < 2; r++) {
        long rowb = (R0 + r0 + 32 * r) * 8;
#pragma unroll
        for (int q = 0; q < 8; q++) {
            float2 a = unpack2(acc[r][2 * q]);
            float2 b = unpack2(acc[r][2 * q + 1]);
            out4[rowb + q] = make_float4(a.x, a.y, b.x, b.y);
        }
    }
}

// ============================================================================
extern "C" void kernel_launch(void* const* d_in, const int* in_sizes, int n_in,
                              void* d_out, int out_size) {
    const float4* in4 = (const float4*)d_in[0];
    float4* out4 = (float4*)d_out;

    k1_stats<<<P1_GRID, 256>>>(in4);
    k_red<<<GROUPS * RED_SLICES, 256>>>();
    k_solve<<<GROUPS, 1024>>>();
    k2_apply<<<P2_GRID, P2_TPB>>>(in4, out4);
}

// round 7
// speedup vs baseline: 1.4338x; 1.4338x over previous
#include <cuda_runtime.h>
#include <cstdint>

typedef unsigned long long u64;

#define GROUPS 8
#define CDIM 32
#define ROWS_PER_GROUP 262144
#define TOTAL_ROWS (GROUPS * ROWS_PER_GROUP)
#define EPSV 1e-5f
#define TITER 5

// ---- pass 1 config (R4 design) ----
#define P1_BLOCKS_PER_GROUP 256
#define P1_GRID (GROUPS * P1_BLOCKS_PER_GROUP)   // 2048
#define P1_ROWS 1024
#define P1_WROWS 128
#define P1_CHUNK 16
#define P1_CHUNKS (P1_WROWS / P1_CHUNK)          // 8
#define PSTRIDE 34                               // u64 per staged pair row
#define WBUF_U64 (8 * PSTRIDE)

// ---- reduction stage ----
#define RED_SLICES 32
#define RED_FOLD (P1_BLOCKS_PER_GROUP / RED_SLICES)

// ---- pass 2 config: 128 threads, 256 rows, 8 rows/thread ----
#define P2_TPB 128
#define P2_ROWS 256
#define P2_GRID (TOTAL_ROWS / P2_ROWS)           // 8192
#define ZST 34

// ---- scratch ----
__device__ __align__(16) float gCovPart[P1_GRID * 1024];
__device__ __align__(16) float gSumPart[P1_GRID * 32];
__device__ __align__(16) float gCov2[GROUPS * RED_SLICES * 1024];
__device__ __align__(16) float gSum2[GROUPS * RED_SLICES * 32];
__device__ __align__(16) float gMt[GROUPS * 1024];
__device__ __align__(16) float gBias[GROUPS * 32];

// ---- f32x2 helpers ----
__device__ __forceinline__ u64 pack2(float a, float b) {
    u64 r; asm("mov.b64 %0, {%1, %2};" : "=l"(r) : "f"(a), "f"(b)); return r;
}
__device__ __forceinline__ float2 unpack2(u64 v) {
    float2 r; asm("mov.b64 {%0, %1}, %2;" : "=f"(r.x), "=f"(r.y) : "l"(v)); return r;
}
__device__ __forceinline__ u64 ffma2(u64 a, u64 b, u64 c) {
    u64 d; asm("fma.rn.f32x2 %0, %1, %2, %3;" : "=l"(d) : "l"(a), "l"(b), "l"(c)); return d;
}

// ============================================================================
// Kernel 1: partial C = sum z z^T + channel sums (R4 design, measured ~118us).
// ============================================================================
__global__ __launch_bounds__(256, 2) void k1_stats(const float4* __restrict__ in4) {
    __shared__ __align__(16) unsigned char smem_raw[32768];
    float* red = (float*)smem_raw;

    const int t   = threadIdx.x;
    const int bid = blockIdx.x;
    const int w   = t >> 5;
    const int l   = t & 31;
    const int a   = l >> 3;
    const int b   = l & 7;
    const int k   = l & 7;
    const int p0  = l >> 3;

    u64* wbuf = (u64*)(smem_raw + w * (WBUF_U64 * 8));

    u64 acc[8][4];
#pragma unroll
    for (int i = 0; i < 8; i++)
#pragma unroll
        for (int j = 0; j < 4; j++) acc[i][j] = 0ull;

    float msum[4] = {0.f, 0.f, 0.f, 0.f};

    const long wbase4 = (long)bid * (P1_ROWS * 8) + (long)w * (P1_WROWS * 8);

    float4 va0 = in4[wbase4 + (2 * p0) * 8 + k];
    float4 vb0 = in4[wbase4 + (2 * p0 + 1) * 8 + k];
    float4 va1 = in4[wbase4 + (2 * (p0 + 4)) * 8 + k];
    float4 vb1 = in4[wbase4 + (2 * (p0 + 4) + 1) * 8 + k];

    for (int c = 0; c < P1_CHUNKS; c++) {
        __syncwarp();
        {
            msum[0] += va0.x + vb0.x + va1.x + vb1.x;
            msum[1] += va0.y + vb0.y + va1.y + vb1.y;
            msum[2] += va0.z + vb0.z + va1.z + vb1.z;
            msum[3] += va0.w + vb0.w + va1.w + vb1.w;
            ulonglong2* dst0 = (ulonglong2*)(wbuf + p0 * PSTRIDE + 4 * k);
            dst0[0] = make_ulonglong2(pack2(va0.x, vb0.x), pack2(va0.y, vb0.y));
            dst0[1] = make_ulonglong2(pack2(va0.z, vb0.z), pack2(va0.w, vb0.w));
            ulonglong2* dst1 = (ulonglong2*)(wbuf + (p0 + 4) * PSTRIDE + 4 * k);
            dst1[0] = make_ulonglong2(pack2(va1.x, vb1.x), pack2(va1.y, vb1.y));
            dst1[1] = make_ulonglong2(pack2(va1.z, vb1.z), pack2(va1.w, vb1.w));
        }
        if (c + 1 < P1_CHUNKS) {
            long nb = wbase4 + (long)(c + 1) * (P1_CHUNK * 8);
            va0 = in4[nb + (2 * p0) * 8 + k];
            vb0 = in4[nb + (2 * p0 + 1) * 8 + k];
            va1 = in4[nb + (2 * (p0 + 4)) * 8 + k];
            vb1 = in4[nb + (2 * (p0 + 4) + 1) * 8 + k];
        }
        __syncwarp();
#pragma unroll
        for (int p = 0; p < 8; p++) {
            const ulonglong2* rowp = (const ulonglong2*)(wbuf + p * PSTRIDE);
            u64 zi[8], zj[4];
#pragma unroll
            for (int i = 0; i < 4; i++) {
                ulonglong2 v = rowp[(8 * a) / 2 + i];
                zi[2 * i] = v.x; zi[2 * i + 1] = v.y;
            }
#pragma unroll
            for (int j = 0; j < 2; j++) {
                ulonglong2 v = rowp[(4 * b) / 2 + j];
                zj[2 * j] = v.x; zj[2 * j + 1] = v.y;
            }
#pragma unroll
            for (int i = 0; i < 8; i++)
#pragma unroll
                for (int j = 0; j < 4; j++)
                    acc[i][j] = ffma2(zi[i], zj[j], acc[i][j]);
        }
    }
    __syncthreads();
#pragma unroll
    for (int i = 0; i < 8; i++)
#pragma unroll
        for (int j = 0; j < 4; j++) {
            float2 x = unpack2(acc[i][j]);
            red[w * 1024 + (8 * a + i) * 32 + (4 * b + j)] = x.x + x.y;
        }
    __syncthreads();
#pragma unroll
    for (int r = 0; r < 4; r++) {
        int e = t + 256 * r;
        float s = 0.f;
#pragma unroll
        for (int ww = 0; ww < 8; ww++) s += red[ww * 1024 + e];
        gCovPart[(long)bid * 1024 + e] = s;
    }
    __syncthreads();
    red[t * 4 + 0] = msum[0]; red[t * 4 + 1] = msum[1];
    red[t * 4 + 2] = msum[2]; red[t * 4 + 3] = msum[3];
    __syncthreads();
    if (t < 32) {
        int kk = t >> 2, i = t & 3;
        float s = 0.f;
#pragma unroll 8
        for (int q = 0; q < 32; q++) s += red[(q * 8 + kk) * 4 + i];
        gSumPart[bid * 32 + t] = s;
    }
}

// ============================================================================
// Kernel 1b: fold 2048 partials -> 256
// ============================================================================
__global__ __launch_bounds__(256) void k_red() {
    const int t = threadIdx.x;
    const int bid = blockIdx.x;
    const long base = (long)bid * RED_FOLD;

#pragma unroll
    for (int r = 0; r < 4; r++) {
        int e = t + 256 * r;
        float s = 0.f;
#pragma unroll
        for (int f = 0; f < RED_FOLD; f++) s += gCovPart[(base + f) * 1024 + e];
        gCov2[(long)bid * 1024 + e] = s;
    }
    if (t < 32) {
        float s = 0.f;
#pragma unroll
        for (int f = 0; f < RED_FOLD; f++) s += gSumPart[(base + f) * 32 + t];
        gSum2[bid * 32 + t] = s;
    }
}

// ============================================================================
// Kernel 2: final reduce, build S, normalize, Newton-Schulz, emit Mt+bias.
// ============================================================================
__global__ __launch_bounds__(1024) void k_solve() {
    __shared__ float S[1024], B[1024], T1[1024], T2[1024];
    __shared__ float mu[32];
    __shared__ float redw[32];
    __shared__ float normsh;

    const int t = threadIdx.x;
    const int g = blockIdx.x;
    const int i = t >> 5, j = t & 31;

    float cv = 0.f;
    const float* cp = gCov2 + (long)g * RED_SLICES * 1024;
#pragma unroll 8
    for (int bb = 0; bb < RED_SLICES; bb++) cv += cp[bb * 1024 + t];
    if (t < 32) {
        float s = 0.f;
        const float* sp = gSum2 + g * RED_SLICES * 32;
#pragma unroll 8
        for (int bb = 0; bb < RED_SLICES; bb++) s += sp[bb * 32 + t];
        mu[t] = s * (1.0f / (float)ROWS_PER_GROUP);
    }
    __syncthreads();

    float sij = cv - (float)ROWS_PER_GROUP * mu[i] * mu[j] + ((i == j) ? EPSV : 0.f);

    float v = sij * sij;
#pragma unroll
    for (int o = 16; o; o >>= 1) v += __shfl_xor_sync(0xffffffffu, v, o);
    if (j == 0) redw[i] = v;
    __syncthreads();
    if (t < 32) {
        float x = redw[t];
#pragma unroll
        for (int o = 16; o; o >>= 1) x += __shfl_xor_sync(0xffffffffu, x, o);
        if (t == 0) normsh = sqrtf(x);
    }
    __syncthreads();
    const float nrm = normsh;

    S[t] = sij / nrm;
    B[t] = (i == j) ? 1.f : 0.f;
    __syncthreads();

    for (int it = 0; it < TITER; it++) {
        float s1 = 0.f;
#pragma unroll
        for (int kk = 0; kk < 32; kk++) s1 += B[i * 32 + kk] * B[kk * 32 + j];
        T1[t] = s1; __syncthreads();
        float s2 = 0.f;
#pragma unroll
        for (int kk = 0; kk < 32; kk++) s2 += T1[i * 32 + kk] * B[kk * 32 + j];
        T2[t] = s2; __syncthreads();
        float s3 = 0.f;
#pragma unroll
        for (int kk = 0; kk < 32; kk++) s3 += T2[i * 32 + kk] * S[kk * 32 + j];
        float nb = 1.5f * B[t] - 0.5f * s3;
        __syncthreads();
        B[t] = nb;
        __syncthreads();
    }

    const float inv = rsqrtf(nrm);
    float mt = B[j * 32 + i] * inv;
    gMt[g * 1024 + t] = mt;
    T1[t] = mt;
    __syncthreads();
    if (t < 32) {
        float bsum = 0.f;
#pragma unroll
        for (int d = 0; d < 32; d++) bsum += mu[d] * T1[d * 32 + t];
        gBias[g * 32 + t] = -bsum;
    }
}

// ============================================================================
// Kernel 3: out[n] = z[n] @ Mt + bias. R5 mapping, Mt amortized over 8 rows.
// 128 threads: m = t&3 (channels 8m..8m+7), q = t>>2 (0..31),
// rows q + 32*rr, rr<8. Per dp: 4 LDS.128 Mt (quad-broadcast) serve 8 rows;
// z via 8 lane-distinct LDS.64. smem bytes/row: 1664 -> 1152.
// ============================================================================
__global__ __launch_bounds__(P2_TPB, 3) void k2_apply(const float4* __restrict__ in4,
                                                      float4* __restrict__ out4) {
    __shared__ __align__(16) float zbuf[P2_ROWS * ZST];  // 34816 B
    __shared__ __align__(16) u64 mt2[512];
    __shared__ u64 bias2[16];

    const int t = threadIdx.x;
    const int g = blockIdx.x >> 10;          // 1024 blocks per group

    const u64* mtg = (const u64*)gMt + g * 512;
#pragma unroll
    for (int i = 0; i < 4; i++) mt2[t + 128 * i] = mtg[t + 128 * i];
    if (t < 16) bias2[t] = ((const u64*)gBias)[g * 16 + t];

    const int m = t & 3;
    const int q = t >> 2;                    // 0..31
    const long R0 = (long)blockIdx.x * P2_ROWS;

    // ---- stage 256 rows: coalesced LDG.128, float2 smem stores ----
#pragma unroll
    for (int i = 0; i < 16; i++) {
        int f = t + 128 * i;                 // float4 id in tile
        int row = f >> 3, sl = f & 7;
        float4 v = in4[R0 * 8 + f];
        float2* d = (float2*)(zbuf + row * ZST + 4 * sl);
        d[0] = make_float2(v.x, v.y);
        d[1] = make_float2(v.z, v.w);
    }
    __syncthreads();

    u64 acc[8][4];
#pragma unroll
    for (int rr = 0; rr < 8; rr++)
#pragma unroll
        for (int jj = 0; jj < 4; jj++) acc[rr][jj] = bias2[m * 4 + jj];

    const ulonglong2* mtv = (const ulonglong2*)mt2;
#pragma unroll 4
    for (int dp = 0; dp < 16; dp++) {
        const int d0 = 2 * dp;
        ulonglong2 ma0 = mtv[d0 * 8 + m * 2 + 0];
        ulonglong2 mb0 = mtv[d0 * 8 + m * 2 + 1];
        ulonglong2 ma1 = mtv[d0 * 8 + m * 2 + 8];   // (d0+1)
        ulonglong2 mb1 = mtv[d0 * 8 + m * 2 + 9];
#pragma unroll
        for (int rr = 0; rr < 8; rr++) {
            float2 z2 = *(const float2*)(zbuf + (q + 32 * rr) * ZST + d0);
            u64 zz0 = pack2(z2.x, z2.x);
            u64 zz1 = pack2(z2.y, z2.y);
            acc[rr][0] = ffma2(zz0, ma0.x, acc[rr][0]);
            acc[rr][1] = ffma2(zz0, ma0.y, acc[rr][1]);
            acc[rr][2] = ffma2(zz0, mb0.x, acc[rr][2]);
            acc[rr][3] = ffma2(zz0, mb0.y, acc[rr][3]);
            acc[rr][0] = ffma2(zz1, ma1.x, acc[rr][0]);
            acc[rr][1] = ffma2(zz1, ma1.y, acc[rr][1]);
            acc[rr][2] = ffma2(zz1, mb1.x, acc[rr][2]);
            acc[rr][3] = ffma2(zz1, mb1.y, acc[rr][3]);
        }
    }

#pragma unroll
    for (int rr = 0; rr < 8; rr++) {
        float2 p0 = unpack2(acc[rr][0]), p1 = unpack2(acc[rr][1]);
        float2 p2 = unpack2(acc[rr][2]), p3 = unpack2(acc[rr][3]);
        long rowb = (R0 + q + 32 * rr) * 8;
        out4[rowb + m * 2 + 0] = make_float4(p0.x, p0.y, p1.x, p1.y);
        out4[rowb + m * 2 + 1] = make_float4(p2.x, p2.y, p3.x, p3.y);
    }
}

// ============================================================================
extern "C" void kernel_launch(void* const* d_in, const int* in_sizes, int n_in,
                              void* d_out, int out_size) {
    const float4* in4 = (const float4*)d_in[0];
    float4* out4 = (float4*)d_out;

    k1_stats<<<P1_GRID, 256>>>(in4);
    k_red<<<GROUPS * RED_SLICES, 256>>>();
    k_solve<<<GROUPS, 1024>>>();
    k2_apply<<<P2_GRID, P2_TPB>>>(in4, out4);
}